// round 5
// baseline (speedup 1.0000x reference)
#include <cuda_runtime.h>
#include <math.h>
#include <math_constants.h>

#define D_MODEL 768
#define N_BR    4
#define DH      64
#define H_TOT   48
#define BATCH   2
#define T_LEN   1024
#define M_ROWS  2048
#define NQ      3072

typedef unsigned long long u64;
typedef unsigned int u32;

// ---- packed fp32x2 helpers ----
__device__ __forceinline__ u64 f2fma(u64 a, u64 b, u64 c) {
    u64 d; asm("fma.rn.f32x2 %0, %1, %2, %3;" : "=l"(d) : "l"(a), "l"(b), "l"(c)); return d;
}
__device__ __forceinline__ u64 f2pack(float lo, float hi) {
    u64 d; asm("mov.b64 %0, {%1, %2};" : "=l"(d) : "f"(lo), "f"(hi)); return d;
}
__device__ __forceinline__ float2 f2unpack(u64 a) {
    float lo, hi; asm("mov.b64 {%0, %1}, %2;" : "=f"(lo), "=f"(hi) : "l"(a)); return make_float2(lo, hi);
}
__device__ __forceinline__ float f2sum(u64 a) { float2 v = f2unpack(a); return v.x + v.y; }

// ---- tf32 split ----
__device__ __forceinline__ float2 tf32split(float x) {
    u32 hb; asm("cvt.rna.tf32.f32 %0, %1;" : "=r"(hb) : "f"(x));
    float hf = __uint_as_float(hb);
    float lo = x - hf;
    u32 lb; asm("cvt.rna.tf32.f32 %0, %1;" : "=r"(lb) : "f"(lo));
    return make_float2(hf, __uint_as_float(lb));
}

#define MMA_TF32(ACC, A0, A1, A2, A3, B0, B1)                                        \
    asm volatile("mma.sync.aligned.m16n8k8.row.col.f32.tf32.tf32.f32 "               \
                 "{%0,%1,%2,%3}, {%4,%5,%6,%7}, {%8,%9}, {%0,%1,%2,%3};"             \
                 : "+f"(ACC[0]), "+f"(ACC[1]), "+f"(ACC[2]), "+f"(ACC[3])            \
                 : "r"(A0), "r"(A1), "r"(A2), "r"(A3), "r"(B0), "r"(B1))

// ---- scratch ----
__device__ float2 g_wq2 [NQ * D_MODEL];       // folded WQ, split
__device__ float2 g_wk2 [NQ * D_MODEL];       // folded WK (48 head-variants), split
__device__ float  g_bk2 [NQ];                 // folded K bias
__device__ float2 g_wot2[D_MODEL * NQ];       // WO as [n][br*768+c], split
__device__ float2 g_A2  [M_ROWS * D_MODEL];   // A split
__device__ float2 g_X2  [M_ROWS * D_MODEL];   // X split
__device__ float  g_qrope[M_ROWS * NQ];       // [bh][t][d]
__device__ float  g_krope[M_ROWS * NQ];
__device__ float2 g_ctx2[(size_t)M_ROWS * NQ];// [b*1024+t][br*768+c], split
__device__ float2 g_ropetab[T_LEN * 32];
__device__ int4   g_topi [BATCH * H_TOT * T_LEN];
__device__ float4 g_topw [BATCH * H_TOT * T_LEN];
__device__ float  g_psink[BATCH * H_TOT * T_LEN];

// ================= prep_w: fold wedge into WQ/WK (+bias), relayout+split WO ======
// blocks [0,576): fold WQ head h=blk/12, c-chunk (blk%12)*64
// blocks [576,1152): fold WK (48 head-variants) + bk2
// blocks [1152,3456): transpose+split WO
__global__ __launch_bounds__(256) void prep_w(const float* __restrict__ WQw,
                                              const float* __restrict__ WKw,
                                              const float* __restrict__ WKb,
                                              const float* __restrict__ wedgeA,
                                              const float* __restrict__ wbias,
                                              const float* __restrict__ WOw) {
    __shared__ float sk[4096];
    __shared__ float Ws[64 * 68];
    __shared__ float tile[32][33];
    const int blk = blockIdx.x, tid = threadIdx.x;

    if (blk < 1152) {
        const bool isK = blk >= 576;
        const int b2 = isK ? blk - 576 : blk;
        const int h = b2 / 12, c0 = (b2 % 12) * 64;
        const int hs = isK ? (h % 12) : h;
        const float* Wsrc = isK ? WKw : WQw;
        for (int i = tid; i < 4096; i += 256) {
            int e = i >> 6, d = i & 63;
            sk[i] = wedgeA[e * 64 + d] - wedgeA[d * 64 + e];
        }
        for (int i = tid; i < 4096; i += 256) {
            int e = i >> 6, c = i & 63;
            Ws[e * 68 + c] = Wsrc[(size_t)(hs * 64 + e) * D_MODEL + c0 + c];
        }
        __syncthreads();
        const int d = tid >> 2, cg = (tid & 3) * 16;
        float outv[16];
        const float bd = 1.0f + wbias[h * 64 + d];
#pragma unroll
        for (int u = 0; u < 16; u++) outv[u] = bd * Ws[d * 68 + cg + u];
        for (int e = 0; e < 64; ++e) {
            float s = sk[e * 64 + d];
            const float* wr = &Ws[e * 68 + cg];
#pragma unroll
            for (int u = 0; u < 16; u++) outv[u] = fmaf(s, wr[u], outv[u]);
        }
        float2* dst = (isK ? g_wk2 : g_wq2) + (size_t)(h * 64 + d) * D_MODEL + c0 + cg;
#pragma unroll
        for (int u = 0; u < 16; u++) dst[u] = tf32split(outv[u]);

        if (isK && c0 == 0 && tid < 64) {
            float acc = (1.0f + wbias[h * 64 + tid]) * WKb[hs * 64 + tid];
            for (int s = 0; s < 64; ++s) acc += sk[s * 64 + tid] * WKb[hs * 64 + s];
            g_bk2[h * 64 + tid] = acc;
        }
    } else {
        const int b3 = blk - 1152;
        const int br = b3 / 576, rem = b3 % 576;
        const int cb = (rem / 24) * 32, nb = (rem % 24) * 32;
        const int tx = tid & 31, ty = tid >> 5;
        for (int r = ty; r < 32; r += 8)
            tile[r][tx] = WOw[((size_t)br * D_MODEL + cb + r) * D_MODEL + nb + tx];
        __syncthreads();
        for (int r = ty; r < 32; r += 8)
            g_wot2[(size_t)(nb + r) * NQ + br * D_MODEL + cb + tx] = tf32split(tile[tx][r]);
    }
}

// ================= prep_a: rope table + split A and X ============================
__global__ __launch_bounds__(256) void prep_a(const float* __restrict__ A,
                                              const float* __restrict__ X) {
    const int blk = blockIdx.x, tid = threadIdx.x;
    if (blk < 128) {
        int idx = blk * 256 + tid;
        int t = idx >> 5, i = idx & 31;
        float inv = exp2f(-(float)i * 0.41524101186092034f);
        float fr = (float)t * inv;
        g_ropetab[idx] = make_float2(cosf(fr), sinf(fr));
    } else if (blk < 896) {
        size_t base = (size_t)(blk - 128) * 2048 + tid;
#pragma unroll
        for (int j = 0; j < 8; j++) g_A2[base + j * 256] = tf32split(A[base + j * 256]);
    } else {
        size_t base = (size_t)(blk - 896) * 2048 + tid;
#pragma unroll
        for (int j = 0; j < 8; j++) g_X2[base + j * 256] = tf32split(X[base + j * 256]);
    }
}

// ================= unified tf32-3x NT GEMM, pre-split operands, double-buffered ===
// CTA tile 128(M) x 64(N), 256 thr, warps 4M x 2N, warp tile 32x32, K-step 16.
// MODE 0 (QK): z=0: A2 @ wq2 -> qrope (rope); z=1: X2 @ wk2 + bk2 -> krope (rope)
// MODE 1 (OUT): ctx2 @ wot2, Y = 0.25*acc + 0.25*sum_br WOb
template <int MODE>
__global__ __launch_bounds__(256) void gemm_main(int K, const float* __restrict__ aux,
                                                 float* __restrict__ outp) {
    extern __shared__ float2 smem2[];
    float2* Asm = smem2;            // 2 * 16*132
    float2* Bsm = smem2 + 4224;     // 2 * 16*68

    const int tid = threadIdx.x;
    const int m0 = blockIdx.y * 128, n0 = blockIdx.x * 64;
    const int warpId = tid >> 5, lane = tid & 31;
    const int warpM = warpId & 3, warpN = warpId >> 2;
    const int g = lane >> 2, tg = lane & 3;
    const int sa_m = tid >> 1, sa_k = (tid & 1) * 8;
    const int sb_n = tid & 63, sb_k = (tid >> 6) * 4;

    const float2* Aop;
    const float2* Bop;
    if (MODE == 0) {
        Aop = blockIdx.z ? g_X2 : g_A2;
        Bop = blockIdx.z ? g_wk2 : g_wq2;
    } else {
        Aop = g_ctx2;
        Bop = g_wot2;
    }

    float acc[2][4][4];
#pragma unroll
    for (int mf = 0; mf < 2; mf++)
#pragma unroll
        for (int nf = 0; nf < 4; nf++)
#pragma unroll
            for (int r = 0; r < 4; r++) acc[mf][nf][r] = 0.f;

    const float2* Arow = Aop + (size_t)(m0 + sa_m) * K + sa_k;
    const float2* Brow = Bop + (size_t)(n0 + sb_n) * K + sb_k;

    float4 ra[4], rb[2];
#pragma unroll
    for (int j = 0; j < 4; j++) ra[j] = ((const float4*)Arow)[j];
#pragma unroll
    for (int j = 0; j < 2; j++) rb[j] = ((const float4*)Brow)[j];

    // stage buf 0
    {
        float2* Ab = Asm;
        float2* Bb = Bsm;
#pragma unroll
        for (int j = 0; j < 4; j++) {
            Ab[(sa_k + 2 * j) * 132 + sa_m]     = make_float2(ra[j].x, ra[j].y);
            Ab[(sa_k + 2 * j + 1) * 132 + sa_m] = make_float2(ra[j].z, ra[j].w);
        }
#pragma unroll
        for (int j = 0; j < 2; j++) {
            Bb[(sb_k + 2 * j) * 68 + sb_n]     = make_float2(rb[j].x, rb[j].y);
            Bb[(sb_k + 2 * j + 1) * 68 + sb_n] = make_float2(rb[j].z, rb[j].w);
        }
    }
    __syncthreads();

    int p = 0;
    for (int k0 = 0; k0 < K; k0 += 16) {
        const bool more = (k0 + 16) < K;
        if (more) {
#pragma unroll
            for (int j = 0; j < 4; j++) ra[j] = ((const float4*)(Arow + k0 + 16))[j];
#pragma unroll
            for (int j = 0; j < 2; j++) rb[j] = ((const float4*)(Brow + k0 + 16))[j];
        }
        const float2* Ab = Asm + p * 2112;
        const float2* Bb = Bsm + p * 1088;
#pragma unroll
        for (int ks = 0; ks < 16; ks += 8) {
            float2 fa[2][4];
#pragma unroll
            for (int mf = 0; mf < 2; mf++) {
                const int rI = warpM * 32 + mf * 16 + g;
                const float2* c0p = &Ab[(ks + tg) * 132];
                const float2* c4p = &Ab[(ks + tg + 4) * 132];
                fa[mf][0] = c0p[rI];
                fa[mf][1] = c0p[rI + 8];
                fa[mf][2] = c4p[rI];
                fa[mf][3] = c4p[rI + 8];
            }
            float2 fb[4][2];
#pragma unroll
            for (int nf = 0; nf < 4; nf++) {
                const int cI = warpN * 32 + nf * 8 + g;
                fb[nf][0] = Bb[(ks + tg) * 68 + cI];
                fb[nf][1] = Bb[(ks + tg + 4) * 68 + cI];
            }
#pragma unroll
            for (int mf = 0; mf < 2; mf++) {
                const u32 ah0 = __float_as_uint(fa[mf][0].x), al0 = __float_as_uint(fa[mf][0].y);
                const u32 ah1 = __float_as_uint(fa[mf][1].x), al1 = __float_as_uint(fa[mf][1].y);
                const u32 ah2 = __float_as_uint(fa[mf][2].x), al2 = __float_as_uint(fa[mf][2].y);
                const u32 ah3 = __float_as_uint(fa[mf][3].x), al3 = __float_as_uint(fa[mf][3].y);
#pragma unroll
                for (int nf = 0; nf < 4; nf++) {
                    const u32 bh0 = __float_as_uint(fb[nf][0].x), bl0 = __float_as_uint(fb[nf][0].y);
                    const u32 bh1 = __float_as_uint(fb[nf][1].x), bl1 = __float_as_uint(fb[nf][1].y);
                    MMA_TF32(acc[mf][nf], al0, al1, al2, al3, bh0, bh1);
                    MMA_TF32(acc[mf][nf], ah0, ah1, ah2, ah3, bl0, bl1);
                    MMA_TF32(acc[mf][nf], ah0, ah1, ah2, ah3, bh0, bh1);
                }
            }
        }
        if (more) {
            float2* Ab2 = Asm + (p ^ 1) * 2112;
            float2* Bb2 = Bsm + (p ^ 1) * 1088;
#pragma unroll
            for (int j = 0; j < 4; j++) {
                Ab2[(sa_k + 2 * j) * 132 + sa_m]     = make_float2(ra[j].x, ra[j].y);
                Ab2[(sa_k + 2 * j + 1) * 132 + sa_m] = make_float2(ra[j].z, ra[j].w);
            }
#pragma unroll
            for (int j = 0; j < 2; j++) {
                Bb2[(sb_k + 2 * j) * 68 + sb_n]     = make_float2(rb[j].x, rb[j].y);
                Bb2[(sb_k + 2 * j + 1) * 68 + sb_n] = make_float2(rb[j].z, rb[j].w);
            }
        }
        __syncthreads();
        p ^= 1;
    }

    // ---- epilogue ----
#pragma unroll
    for (int mf = 0; mf < 2; mf++) {
#pragma unroll
        for (int nf = 0; nf < 4; nf++) {
            const int r0 = m0 + warpM * 32 + mf * 16 + g;
            const int r1 = r0 + 8;
            float c0 = acc[mf][nf][0], c1 = acc[mf][nf][1];
            float c2 = acc[mf][nf][2], c3 = acc[mf][nf][3];
            if (MODE == 0) {
                const int h = blockIdx.x;
                const int i = warpN * 16 + nf * 4 + tg;     // rope pair index
                float* outbase = blockIdx.z ? g_krope : g_qrope;
                if (blockIdx.z) {
                    const float b0 = g_bk2[h * 64 + 2 * i];
                    const float b1 = g_bk2[h * 64 + 2 * i + 1];
                    c0 += b0; c1 += b1; c2 += b0; c3 += b1;
                }
                {
                    const int t = r0 & 1023, bb = r0 >> 10;
                    float2 rc = g_ropetab[t * 32 + i];
                    float* qp = &outbase[(((size_t)(bb * H_TOT + h)) * T_LEN + t) * DH];
                    qp[i]      = c0 * rc.x - c1 * rc.y;
                    qp[i + 32] = c0 * rc.y + c1 * rc.x;
                }
                {
                    const int t = r1 & 1023, bb = r1 >> 10;
                    float2 rc = g_ropetab[t * 32 + i];
                    float* qp = &outbase[(((size_t)(bb * H_TOT + h)) * T_LEN + t) * DH];
                    qp[i]      = c2 * rc.x - c3 * rc.y;
                    qp[i + 32] = c2 * rc.y + c3 * rc.x;
                }
            } else {
                const int nc = n0 + warpN * 32 + nf * 8 + 2 * tg;
                const float b0 = 0.25f * (aux[nc] + aux[768 + nc] + aux[1536 + nc] + aux[2304 + nc]);
                const float b1 = 0.25f * (aux[nc + 1] + aux[768 + nc + 1] + aux[1536 + nc + 1] + aux[2304 + nc + 1]);
                *(float2*)&outp[(size_t)r0 * 768 + nc] = make_float2(0.25f * c0 + b0, 0.25f * c1 + b1);
                *(float2*)&outp[(size_t)r1 * 768 + nc] = make_float2(0.25f * c2 + b0, 0.25f * c3 + b1);
            }
        }
    }
}

// ================= attn1: scores + online softmax + top-4 ========================
// 128 thr, grid (8, 96), t-tile 128, k staged 128 rows (32 KB smem)
__global__ __launch_bounds__(128) void attn1_kernel(const float* __restrict__ sink) {
    extern __shared__ float ks[];            // 8192 floats
    const int bh = blockIdx.y;
    const int h = bh % H_TOT;
    const int xt = (gridDim.x - 1) - blockIdx.x;    // heavy tiles first
    const int t = xt * 128 + threadIdx.x;

    u64 q2[32];
    {
        const ulonglong2* qp = (const ulonglong2*)&g_qrope[((size_t)bh * T_LEN + t) * DH];
#pragma unroll
        for (int i = 0; i < 16; i++) { ulonglong2 v = qp[i]; q2[2 * i] = v.x; q2[2 * i + 1] = v.y; }
    }

    float mrun = -CUDART_INF_F, lrun = 0.f;
    float ts0 = -CUDART_INF_F, ts1 = -CUDART_INF_F, ts2 = -CUDART_INF_F, ts3 = -CUDART_INF_F;
    int ti0 = 0, ti1 = 0, ti2 = 0, ti3 = 0;

    const int sEnd = xt * 128 + 127;
    for (int s0 = 0; s0 <= sEnd; s0 += 128) {
        __syncthreads();
        {
            const float4* kg = (const float4*)&g_krope[((size_t)bh * T_LEN + s0) * DH];
            float4* d4 = (float4*)ks;
            for (int i = threadIdx.x; i < 2048; i += 128) d4[i] = kg[i];
        }
        __syncthreads();

        const int sMax = min(t, s0 + 127);
        for (int s = s0; s <= sMax; ++s) {
            const ulonglong2* kr = (const ulonglong2*)(ks + (s - s0) * DH);
            u64 a0 = 0ull, a1 = 0ull, a2 = 0ull, a3 = 0ull;
#pragma unroll
            for (int i = 0; i < 16; i += 2) {
                ulonglong2 kva = kr[i];
                ulonglong2 kvb = kr[i + 1];
                a0 = f2fma(q2[2 * i],     kva.x, a0);
                a1 = f2fma(q2[2 * i + 1], kva.y, a1);
                a2 = f2fma(q2[2 * i + 2], kvb.x, a2);
                a3 = f2fma(q2[2 * i + 3], kvb.y, a3);
            }
            float sc = ((f2sum(a0) + f2sum(a1)) + (f2sum(a2) + f2sum(a3))) * 0.125f;

            if (sc <= mrun) {
                lrun += __expf(sc - mrun);
            } else {
                lrun = fmaf(lrun, __expf(mrun - sc), 1.0f);
                mrun = sc;
            }
            if (sc > ts3) {
                if (sc > ts2) {
                    ts3 = ts2; ti3 = ti2;
                    if (sc > ts1) {
                        ts2 = ts1; ti2 = ti1;
                        if (sc > ts0) {
                            ts1 = ts0; ti1 = ti0;
                            ts0 = sc; ti0 = s;
                        } else { ts1 = sc; ti1 = s; }
                    } else { ts2 = sc; ti2 = s; }
                } else { ts3 = sc; ti3 = s; }
            }
        }
    }

    const float sk = sink[h];
    const float mf = fmaxf(mrun, sk);
    const float Z = lrun * __expf(mrun - mf) + __expf(sk - mf);
    const float invZ = 1.0f / Z;
    const float psink = __expf(sk - mf) * invZ;
    float p0 = __expf(ts0 - mf) * invZ;
    float p1 = __expf(ts1 - mf) * invZ;
    float p2 = __expf(ts2 - mf) * invZ;
    float p3 = __expf(ts3 - mf) * invZ;
    const float winv = 1.0f / (p0 + p1 + p2 + p3 + 1e-9f);
    p0 *= winv; p1 *= winv; p2 *= winv; p3 *= winv;

    const int o = bh * T_LEN + t;
    g_topi[o]  = make_int4(ti0, ti1, ti2, ti3);
    g_topw[o]  = make_float4(p0, p1, p2, p3);
    g_psink[o] = psink;
}

// ================= attn2: marker gather + MLP + ctx write (split) ================
// 512 thr, grid (2, 96); V1 + V2^T staged once per 512 rows
__global__ __launch_bounds__(512) void attn2_kernel(const float* __restrict__ vnull,
                                                    const float* __restrict__ V1w,
                                                    const float* __restrict__ V1b,
                                                    const float* __restrict__ V2w,
                                                    const float* __restrict__ V2b) {
    extern __shared__ float sm2[];
    float* V1s = sm2;                 // 16384
    float* V2t = sm2 + 16384;         // 256*66
    __shared__ float sV1b[256];
    __shared__ float sV2b[64];

    const int bh = blockIdx.y, b = bh / H_TOT, h = bh % H_TOT;
    const int t = blockIdx.x * 512 + threadIdx.x;

    for (int i = threadIdx.x; i < 4096; i += 512) ((float4*)V1s)[i] = ((const float4*)V1w)[i];
    for (int i = threadIdx.x; i < 16384; i += 512) {
        int dd = i >> 8, j = i & 255;
        V2t[j * 66 + dd] = V2w[i];
    }
    if (threadIdx.x < 256) sV1b[threadIdx.x] = V1b[threadIdx.x];
    if (threadIdx.x < 64)  sV2b[threadIdx.x] = V2b[threadIdx.x];
    __syncthreads();

    const int o = bh * T_LEN + t;
    const int4 ti = g_topi[o];
    const float4 pw = g_topw[o];
    const float psink = g_psink[o];

    u64 mk[32];
    {
        u64 w0 = f2pack(pw.x, pw.x), w1 = f2pack(pw.y, pw.y);
        u64 w2 = f2pack(pw.z, pw.z), w3 = f2pack(pw.w, pw.w);
        const ulonglong2* kp0 = (const ulonglong2*)&g_krope[((size_t)bh * T_LEN + ti.x) * DH];
        const ulonglong2* kp1 = (const ulonglong2*)&g_krope[((size_t)bh * T_LEN + ti.y) * DH];
        const ulonglong2* kp2 = (const ulonglong2*)&g_krope[((size_t)bh * T_LEN + ti.z) * DH];
        const ulonglong2* kp3 = (const ulonglong2*)&g_krope[((size_t)bh * T_LEN + ti.w) * DH];
#pragma unroll
        for (int i = 0; i < 16; i++) {
            ulonglong2 va = kp0[i], vb = kp1[i], vc = kp2[i], vd = kp3[i];
            mk[2 * i]     = f2fma(w0, va.x, f2fma(w1, vb.x, f2fma(w2, vc.x, f2fma(w3, vd.x, 0ull))));
            mk[2 * i + 1] = f2fma(w0, va.y, f2fma(w1, vb.y, f2fma(w2, vc.y, f2fma(w3, vd.y, 0ull))));
        }
    }

    u64 out2[32];
#pragma unroll
    for (int i = 0; i < 32; i++) out2[i] = *(const u64*)&sV2b[2 * i];

    for (int j = 0; j < 256; ++j) {
        const ulonglong2* v1 = (const ulonglong2*)(V1s + j * 64);
        u64 z0 = 0ull, z1 = 0ull, z2 = 0ull, z3 = 0ull;
#pragma unroll
        for (int i = 0; i < 16; i += 2) {
            ulonglong2 va = v1[i];
            ulonglong2 vb = v1[i + 1];
            z0 = f2fma(mk[2 * i],     va.x, z0);
            z1 = f2fma(mk[2 * i + 1], va.y, z1);
            z2 = f2fma(mk[2 * i + 2], vb.x, z2);
            z3 = f2fma(mk[2 * i + 3], vb.y, z3);
        }
        float z = ((f2sum(z0) + f2sum(z1)) + (f2sum(z2) + f2sum(z3))) + sV1b[j];
        float gl = 0.5f * z * (1.0f + erff(z * 0.70710678118f));
        u64 g2 = f2pack(gl, gl);
        const u64* v2 = (const u64*)(V2t + j * 66);
#pragma unroll
        for (int i = 0; i < 32; i++) out2[i] = f2fma(g2, v2[i], out2[i]);
    }

    const int br = h / 12, hj = h % 12;
    float2* outp = &g_ctx2[((size_t)(b * T_LEN + t)) * NQ + br * D_MODEL + hj * 64];
    const float* vn = vnull + h * 64;
#pragma unroll
    for (int i = 0; i < 32; i++) {
        float2 v = f2unpack(out2[i]);
        outp[2 * i]     = tf32split(fmaf(psink, vn[2 * i], v.x));
        outp[2 * i + 1] = tf32split(fmaf(psink, vn[2 * i + 1], v.y));
    }
}

// ================= launcher =================
extern "C" void kernel_launch(void* const* d_in, const int* in_sizes, int n_in,
                              void* d_out, int out_size) {
    const float* A      = (const float*)d_in[0];
    const float* X      = (const float*)d_in[1];
    const float* WKw    = (const float*)d_in[2];
    const float* WKb    = (const float*)d_in[3];
    const float* WQw    = (const float*)d_in[4];
    const float* wedgeA = (const float*)d_in[5];
    const float* wbias  = (const float*)d_in[6];
    const float* sink   = (const float*)d_in[7];
    const float* vnull  = (const float*)d_in[8];
    const float* V1w    = (const float*)d_in[9];
    const float* V1b    = (const float*)d_in[10];
    const float* V2w    = (const float*)d_in[11];
    const float* V2b    = (const float*)d_in[12];
    const float* WOw    = (const float*)d_in[13];
    const float* WOb    = (const float*)d_in[14];
    float* Y = (float*)d_out;

    cudaFuncSetAttribute(gemm_main<0>, cudaFuncAttributeMaxDynamicSharedMemorySize, 51200);
    cudaFuncSetAttribute(gemm_main<1>, cudaFuncAttributeMaxDynamicSharedMemorySize, 51200);
    cudaFuncSetAttribute(attn1_kernel, cudaFuncAttributeMaxDynamicSharedMemorySize, 32768);
    cudaFuncSetAttribute(attn2_kernel, cudaFuncAttributeMaxDynamicSharedMemorySize, 133120);

    // 1) weights prep (fold wedge into WQ/WK, WO relayout, tf32 splits)
    prep_w<<<3456, 256>>>(WQw, WKw, WKb, wedgeA, wbias, WOw);
    // 2) activations prep (rope table, split A/X)
    prep_a<<<1664, 256>>>(A, X);
    // 3) Q and K projections + rope, one launch
    gemm_main<0><<<dim3(48, 16, 2), 256, 51200>>>(768, nullptr, nullptr);
    // 4) attention scores / softmax / top-4   (<- ncu capture slot)
    attn1_kernel<<<dim3(8, 96), 128, 32768>>>(sink);
    // 5) marker + MLP + sink, writes split ctx
    attn2_kernel<<<dim3(2, 96), 512, 133120>>>(vnull, V1w, V1b, V2w, V2b);
    // 6) output projection
    gemm_main<1><<<dim3(12, 16, 1), 256, 51200>>>(3072, WOb, Y);
}